// round 1
// baseline (speedup 1.0000x reference)
#include <cuda_runtime.h>
#include <math.h>

#define CK __restrict__

// ---------------- scratch (device globals; no allocation allowed) ----------------
__device__ float g_c1[32 * 64 * 112 * 112];   // conv1 out
__device__ float g_pool[32 * 64 * 56 * 56];   // maxpool out
__device__ float g_c2[32 * 128 * 28 * 28];
__device__ float g_c3[32 * 256 * 14 * 14];
__device__ float g_c4[32 * 512 * 7 * 7];
__device__ float g_scale[512];
__device__ float g_shift[512];
__device__ float g_feats[32 * 512];
__device__ float g_enc[32 * 512];
__device__ float g_h[32 * 512];
__device__ float g_cst[32 * 512];
__device__ float g_xs[640 * 512];     // gathered embeddings, m = b*20+t
__device__ float g_gx[640 * 2048];    // x @ wih^T for all steps
__device__ float g_gh[32 * 2048];     // h @ whh^T per step
__device__ float g_hs[640 * 512];     // all hidden states

// ---------------- conv1: 7x7 stride2 pad3, 3->64, 224->112 ----------------
// grid (28, 64, 32), block 112. Each thread: 4 output rows at its x.
// smem rows stored parity-deinterleaved so stride-2 reads are conflict-free.
__global__ void conv1_k(const float* CK img, const float* CK w) {
    const int y0 = blockIdx.x * 4;
    const int co = blockIdx.y;
    const int n  = blockIdx.z;
    const int x  = threadIdx.x;
    __shared__ float ws[147];
    __shared__ __align__(16) float srow[39][232];  // 39 = 3ci * 13 rows; col addr = (c>>1)+(c&1)*116

    for (int i = x; i < 147; i += 112) ws[i] = w[co * 147 + i];

    for (int r = 0; r < 39; r++) {
        int ci = r / 13, d = r - ci * 13;
        int iy = y0 * 2 - 3 + d;
        const float* src = img + ((n * 3 + ci) * 224 + iy) * 224;
        bool ok = (iy >= 0 && iy < 224);
        for (int c = x; c < 232; c += 112) {
            int xm = c - 3;
            float v = (ok && xm >= 0 && xm < 224) ? src[xm] : 0.f;
            srow[r][(c >> 1) + (c & 1) * 116] = v;
        }
    }
    __syncthreads();

    float acc[4] = {0.f, 0.f, 0.f, 0.f};
#pragma unroll
    for (int ci = 0; ci < 3; ci++) {
#pragma unroll
        for (int ky = 0; ky < 7; ky++) {
            const float* wr = &ws[ci * 49 + ky * 7];
#pragma unroll
            for (int kx = 0; kx < 7; kx++) {
                float wv = wr[kx];
                int col = 2 * x + kx;
                int a = (col >> 1) + (col & 1) * 116;
#pragma unroll
                for (int r = 0; r < 4; r++)
                    acc[r] += srow[ci * 13 + 2 * r + ky][a] * wv;
            }
        }
    }
    float* o = g_c1 + ((n * 64 + co) * 112 + y0) * 112 + x;
#pragma unroll
    for (int r = 0; r < 4; r++) o[r * 112] = acc[r];
}

// ---------------- BN: batch statistics ----------------
__global__ void bn_stats_k(const float* CK x, const float* CK g, const float* CK be,
                           int C, int HW) {
    int c = blockIdx.x, tid = threadIdx.x;
    float s = 0.f, s2 = 0.f;
    for (int n = 0; n < 32; n++) {
        const float* p = x + (size_t)(n * C + c) * HW;
        for (int i = tid; i < HW; i += 256) { float v = p[i]; s += v; s2 += v * v; }
    }
    __shared__ float sh[256], sh2[256];
    sh[tid] = s; sh2[tid] = s2;
    __syncthreads();
    for (int st = 128; st > 0; st >>= 1) {
        if (tid < st) { sh[tid] += sh[tid + st]; sh2[tid] += sh2[tid + st]; }
        __syncthreads();
    }
    if (tid == 0) {
        float inv = 1.f / (32.f * (float)HW);
        float m = sh[0] * inv;
        float var = sh2[0] * inv - m * m;
        float sc = g[c] * rsqrtf(var + 1e-5f);
        g_scale[c] = sc;
        g_shift[c] = be[c] - m * sc;
    }
}

// grid (ceil(HW/256), C, 32)
__global__ void bn_relu_k(float* CK x, int HW) {
    int c = blockIdx.y, n = blockIdx.z;
    int i = blockIdx.x * 256 + threadIdx.x;
    if (i >= HW) return;
    float* p = x + (size_t)(n * gridDim.y + c) * HW;
    float v = p[i] * g_scale[c] + g_shift[c];
    p[i] = v > 0.f ? v : 0.f;
}

// ---------------- maxpool 3x3 s2 pad1: 112 -> 56 ----------------
__global__ void pool_k() {
    int c = blockIdx.y, n = blockIdx.z;
    int p = blockIdx.x * 256 + threadIdx.x;
    if (p >= 56 * 56) return;
    int oy = p / 56, ox = p - oy * 56;
    const float* src = g_c1 + (size_t)((n * 64 + c) * 112) * 112;
    float m = -1e30f;
    int iy0 = oy * 2 - 1, ix0 = ox * 2 - 1;
#pragma unroll
    for (int dy = 0; dy < 3; dy++) {
        int iy = iy0 + dy;
        if (iy < 0 || iy >= 112) continue;
#pragma unroll
        for (int dx = 0; dx < 3; dx++) {
            int ix = ix0 + dx;
            if (ix < 0 || ix >= 112) continue;
            float v = src[iy * 112 + ix];
            m = v > m ? v : m;
        }
    }
    g_pool[((n * 64 + c) * 56 + oy) * 56 + ox] = m;
}

// ---------------- generic 3x3 stride2 pad1 conv, planes in smem ----------------
// grid (COUT/TCO, 32/TN), block NT. Thread: P spatial outputs x TCO chans x TN batches.
template <int CIN, int HIN, int HOUT, int TCO, int TN, int NT, int P>
__global__ void conv3x3s2_k(const float* CK in, const float* CK w, float* CK out, int COUT) {
    const int HIN2 = HIN * HIN, HOUT2 = HOUT * HOUT, HALF = HIN / 2;
    extern __shared__ float sm[];
    float* ws = sm;                       // TCO*CIN*9
    float* pl = sm + TCO * CIN * 9;       // TN * HIN2, rows parity-deinterleaved
    int tid = threadIdx.x;
    int co0 = blockIdx.x * TCO;
    int n0  = blockIdx.y * TN;

    for (int i = tid; i < TCO * CIN * 9; i += NT) {
        int t = i / (CIN * 9), r = i - t * (CIN * 9);
        ws[i] = w[(size_t)(co0 + t) * CIN * 9 + r];
    }

    int oy[P], ox[P];
    int adr[P][9];
#pragma unroll
    for (int p = 0; p < P; p++) {
        int q = tid + p * NT;
        bool v = q < HOUT2;
        oy[p] = v ? q / HOUT : 0;
        ox[p] = v ? q - oy[p] * HOUT : 0;
#pragma unroll
        for (int ky = 0; ky < 3; ky++)
#pragma unroll
            for (int kx = 0; kx < 3; kx++) {
                int iy = oy[p] * 2 - 1 + ky;
                int ix = ox[p] * 2 - 1 + kx;
                bool inb = v && iy >= 0 && iy < HIN && ix >= 0 && ix < HIN;
                adr[p][ky * 3 + kx] = inb ? iy * HIN + (ix >> 1) + (ix & 1) * HALF : -1;
            }
    }

    float acc[TCO][TN][P];
#pragma unroll
    for (int t = 0; t < TCO; t++)
#pragma unroll
        for (int tn = 0; tn < TN; tn++)
#pragma unroll
            for (int p = 0; p < P; p++) acc[t][tn][p] = 0.f;

    for (int ci = 0; ci < CIN; ci++) {
        __syncthreads();
        for (int i = tid; i < TN * HIN2; i += NT) {
            int tn = i / HIN2, r = i - tn * HIN2;
            int iy = r / HIN, ix = r - iy * HIN;
            float v = in[((size_t)(n0 + tn) * CIN + ci) * HIN2 + r];
            pl[tn * HIN2 + iy * HIN + (ix >> 1) + (ix & 1) * HALF] = v;
        }
        __syncthreads();
#pragma unroll
        for (int tap = 0; tap < 9; tap++) {
            float wv[TCO];
#pragma unroll
            for (int t = 0; t < TCO; t++) wv[t] = ws[t * CIN * 9 + ci * 9 + tap];
#pragma unroll
            for (int p = 0; p < P; p++) {
                int a = adr[p][tap];
                if (a >= 0) {
#pragma unroll
                    for (int tn = 0; tn < TN; tn++) {
                        float v = pl[tn * HIN2 + a];
#pragma unroll
                        for (int t = 0; t < TCO; t++) acc[t][tn][p] += v * wv[t];
                    }
                }
            }
        }
    }

#pragma unroll
    for (int p = 0; p < P; p++) {
        int q = tid + p * NT;
        if (q < HOUT2) {
#pragma unroll
            for (int tn = 0; tn < TN; tn++)
#pragma unroll
                for (int t = 0; t < TCO; t++)
                    out[((size_t)(n0 + tn) * COUT + co0 + t) * HOUT2 + q] = acc[t][tn][p];
        }
    }
}

// ---------------- global average pool 7x7 ----------------
__global__ void avgpool_k() {
    int n = blockIdx.x, c = threadIdx.x;
    const float* p = g_c4 + (size_t)(n * 512 + c) * 49;
    float s = 0.f;
#pragma unroll
    for (int i = 0; i < 49; i++) s += p[i];
    g_feats[n * 512 + c] = s * (1.f / 49.f);
}

// ---------------- enc = feats @ pw + pb ----------------
__global__ void enc_k(const float* CK pw, const float* CK pb) {
    int n = blockIdx.x, o = threadIdx.x;
    __shared__ float fr[512];
    fr[o] = g_feats[n * 512 + o];
    __syncthreads();
    float acc = pb[o];
    for (int k = 0; k < 512; k++) acc += fr[k] * pw[k * 512 + o];
    g_enc[n * 512 + o] = acc;
}

// ---------------- h0 = tanh(enc@ihw+ihb), c0 = tanh(enc@icw+icb) ----------------
__global__ void h0c0_k(const float* CK ihw, const float* CK ihb,
                       const float* CK icw, const float* CK icb) {
    int n = blockIdx.x, o = threadIdx.x;
    __shared__ float er[512];
    er[o] = g_enc[n * 512 + o];
    __syncthreads();
    float ah = ihb[o], ac = icb[o];
    for (int k = 0; k < 512; k++) {
        float e = er[k];
        ah += e * ihw[k * 512 + o];
        ac += e * icw[k * 512 + o];
    }
    g_h[n * 512 + o]   = tanhf(ah);
    g_cst[n * 512 + o] = tanhf(ac);
}

// ---------------- gather embeddings for all steps ----------------
__global__ void xgather_k(const float* CK emb, const int* CK caps) {
    int m = blockIdx.x;                // 0..639
    int b = m / 20, t = m - b * 20;
    int tok = caps[b * 21 + t];
    g_xs[m * 512 + threadIdx.x] = emb[(size_t)tok * 512 + threadIdx.x];
}

// ---------------- tiled SGEMM: BM=64 BN=128 BK=16, 256 threads, 4x8 regs ----------------
// TRANSB=0: B is [K,N]. TRANSB=1: B is [N,K] (computes A @ B^T).
template <int TRANSB>
__global__ void gemm128_k(const float* CK A, const float* CK Bm, const float* CK bias,
                          float* CK Cm, int M, int N, int K) {
    __shared__ __align__(16) float As[16][64];
    __shared__ __align__(16) float Bs[16][128];
    int tid = threadIdx.x;
    int n0 = blockIdx.x * 128;
    int m0 = blockIdx.y * 64;
    int tx = tid & 15, ty = tid >> 4;
    float acc[4][8];
#pragma unroll
    for (int i = 0; i < 4; i++)
#pragma unroll
        for (int j = 0; j < 8; j++) acc[i][j] = 0.f;

    int ar = tid >> 2, aq = (tid & 3) * 4;
    for (int k0 = 0; k0 < K; k0 += 16) {
        float4 av = *(const float4*)(A + (size_t)(m0 + ar) * K + k0 + aq);
        As[aq + 0][ar] = av.x; As[aq + 1][ar] = av.y;
        As[aq + 2][ar] = av.z; As[aq + 3][ar] = av.w;
        if (TRANSB) {
            int bn = tid >> 1, bq = (tid & 1) * 8;
            float4 b0 = *(const float4*)(Bm + (size_t)(n0 + bn) * K + k0 + bq);
            float4 b1 = *(const float4*)(Bm + (size_t)(n0 + bn) * K + k0 + bq + 4);
            Bs[bq + 0][bn] = b0.x; Bs[bq + 1][bn] = b0.y; Bs[bq + 2][bn] = b0.z; Bs[bq + 3][bn] = b0.w;
            Bs[bq + 4][bn] = b1.x; Bs[bq + 5][bn] = b1.y; Bs[bq + 6][bn] = b1.z; Bs[bq + 7][bn] = b1.w;
        } else {
            int br = tid >> 4, bc = (tid & 15) * 8;
            float4 b0 = *(const float4*)(Bm + (size_t)(k0 + br) * N + n0 + bc);
            float4 b1 = *(const float4*)(Bm + (size_t)(k0 + br) * N + n0 + bc + 4);
            *(float4*)&Bs[br][bc] = b0;
            *(float4*)&Bs[br][bc + 4] = b1;
        }
        __syncthreads();
#pragma unroll
        for (int k = 0; k < 16; k++) {
            float4 a4 = *(const float4*)&As[k][ty * 4];
            float4 b4 = *(const float4*)&Bs[k][tx * 8];
            float4 b5 = *(const float4*)&Bs[k][tx * 8 + 4];
            float aa[4] = {a4.x, a4.y, a4.z, a4.w};
            float bb[8] = {b4.x, b4.y, b4.z, b4.w, b5.x, b5.y, b5.z, b5.w};
#pragma unroll
            for (int i = 0; i < 4; i++)
#pragma unroll
                for (int j = 0; j < 8; j++) acc[i][j] += aa[i] * bb[j];
        }
        __syncthreads();
    }
#pragma unroll
    for (int i = 0; i < 4; i++) {
        int m = m0 + ty * 4 + i;
        float* crow = Cm + (size_t)m * N + n0 + tx * 8;
#pragma unroll
        for (int j = 0; j < 8; j++) {
            float v = acc[i][j];
            if (bias) v += bias[n0 + tx * 8 + j];
            crow[j] = v;
        }
    }
}

// ---------------- per-step h GEMM: g_gh[32,2048] = g_h[32,512] @ whh^T ----------------
// BM=32 BN=64 BK=16, 128 threads, grid 32
__global__ void gemm_h_k(const float* CK Bm /*whh [2048,512]*/) {
    __shared__ __align__(16) float As[16][32];
    __shared__ __align__(16) float Bs[16][64];
    int tid = threadIdx.x;
    int n0 = blockIdx.x * 64;
    int tx = tid & 15, ty = tid >> 4;  // ty 0..7
    float acc[4][4];
#pragma unroll
    for (int i = 0; i < 4; i++)
#pragma unroll
        for (int j = 0; j < 4; j++) acc[i][j] = 0.f;

    int ar = tid >> 2, aq = (tid & 3) * 4;   // ar 0..31
    int bn = tid >> 1, bq = (tid & 1) * 8;   // bn 0..63
    for (int k0 = 0; k0 < 512; k0 += 16) {
        float4 av = *(const float4*)(g_h + ar * 512 + k0 + aq);
        As[aq + 0][ar] = av.x; As[aq + 1][ar] = av.y;
        As[aq + 2][ar] = av.z; As[aq + 3][ar] = av.w;
        float4 b0 = *(const float4*)(Bm + (size_t)(n0 + bn) * 512 + k0 + bq);
        float4 b1 = *(const float4*)(Bm + (size_t)(n0 + bn) * 512 + k0 + bq + 4);
        Bs[bq + 0][bn] = b0.x; Bs[bq + 1][bn] = b0.y; Bs[bq + 2][bn] = b0.z; Bs[bq + 3][bn] = b0.w;
        Bs[bq + 4][bn] = b1.x; Bs[bq + 5][bn] = b1.y; Bs[bq + 6][bn] = b1.z; Bs[bq + 7][bn] = b1.w;
        __syncthreads();
#pragma unroll
        for (int k = 0; k < 16; k++) {
            float4 a4 = *(const float4*)&As[k][ty * 4];
            float4 b4 = *(const float4*)&Bs[k][tx * 4];
            float aa[4] = {a4.x, a4.y, a4.z, a4.w};
            float bb[4] = {b4.x, b4.y, b4.z, b4.w};
#pragma unroll
            for (int i = 0; i < 4; i++)
#pragma unroll
                for (int j = 0; j < 4; j++) acc[i][j] += aa[i] * bb[j];
        }
        __syncthreads();
    }
#pragma unroll
    for (int i = 0; i < 4; i++)
#pragma unroll
        for (int j = 0; j < 4; j++)
            g_gh[(ty * 4 + i) * 2048 + n0 + tx * 4 + j] = acc[i][j];
}

// ---------------- LSTM pointwise ----------------
__device__ __forceinline__ float sigf(float x) { return 1.f / (1.f + expf(-x)); }

__global__ void lstm_point_k(const float* CK bih, const float* CK bhh, int t) {
    int idx = blockIdx.x * 256 + threadIdx.x;   // 16384
    int b = idx >> 9, j = idx & 511;
    int m = b * 20 + t;
    const float* gx = g_gx + (size_t)m * 2048;
    const float* gh = g_gh + b * 2048;
    float iv = gx[j]        + gh[j]        + bih[j]        + bhh[j];
    float fv = gx[512 + j]  + gh[512 + j]  + bih[512 + j]  + bhh[512 + j];
    float gv = gx[1024 + j] + gh[1024 + j] + bih[1024 + j] + bhh[1024 + j];
    float ov = gx[1536 + j] + gh[1536 + j] + bih[1536 + j] + bhh[1536 + j];
    float c = g_cst[idx];
    c = sigf(fv) * c + sigf(iv) * tanhf(gv);
    float h = sigf(ov) * tanhf(c);
    g_cst[idx] = c;
    g_h[idx] = h;
    g_hs[(size_t)m * 512 + j] = h;
}

// ---------------- launch ----------------
extern "C" void kernel_launch(void* const* d_in, const int* in_sizes, int n_in,
                              void* d_out, int out_size) {
    const float* images = (const float*)d_in[0];
    const int*   caps   = (const int*)d_in[1];
    const float* w1  = (const float*)d_in[2];
    const float* g1  = (const float*)d_in[3];
    const float* be1 = (const float*)d_in[4];
    const float* w2  = (const float*)d_in[5];
    const float* g2  = (const float*)d_in[6];
    const float* be2 = (const float*)d_in[7];
    const float* w3  = (const float*)d_in[8];
    const float* g3  = (const float*)d_in[9];
    const float* be3 = (const float*)d_in[10];
    const float* w4  = (const float*)d_in[11];
    const float* g4  = (const float*)d_in[12];
    const float* be4 = (const float*)d_in[13];
    const float* pw  = (const float*)d_in[14];
    const float* pb  = (const float*)d_in[15];
    const float* emb = (const float*)d_in[16];
    const float* ihw = (const float*)d_in[17];
    const float* ihb = (const float*)d_in[18];
    const float* icw = (const float*)d_in[19];
    const float* icb = (const float*)d_in[20];
    const float* wih = (const float*)d_in[21];
    const float* whh = (const float*)d_in[22];
    const float* bih = (const float*)d_in[23];
    const float* bhh = (const float*)d_in[24];
    const float* ow  = (const float*)d_in[25];
    const float* ob  = (const float*)d_in[26];

    float *pC1, *pPool, *pC2, *pC3, *pC4, *pXs, *pGx, *pHs;
    cudaGetSymbolAddress((void**)&pC1, g_c1);
    cudaGetSymbolAddress((void**)&pPool, g_pool);
    cudaGetSymbolAddress((void**)&pC2, g_c2);
    cudaGetSymbolAddress((void**)&pC3, g_c3);
    cudaGetSymbolAddress((void**)&pC4, g_c4);
    cudaGetSymbolAddress((void**)&pXs, g_xs);
    cudaGetSymbolAddress((void**)&pGx, g_gx);
    cudaGetSymbolAddress((void**)&pHs, g_hs);

    // ---- conv1 + BN + ReLU + maxpool ----
    conv1_k<<<dim3(28, 64, 32), 112>>>(images, w1);
    bn_stats_k<<<64, 256>>>(pC1, g1, be1, 64, 112 * 112);
    bn_relu_k<<<dim3(49, 64, 32), 256>>>(pC1, 112 * 112);
    pool_k<<<dim3(13, 64, 32), 256>>>();

    // ---- conv2 (64->128, 56->28) ----
    {
        int smem = (4 * 64 * 9 + 1 * 56 * 56) * 4;
        conv3x3s2_k<64, 56, 28, 4, 1, 256, 4><<<dim3(128 / 4, 32), 256, smem>>>(pPool, w2, pC2, 128);
        bn_stats_k<<<128, 256>>>(pC2, g2, be2, 128, 28 * 28);
        bn_relu_k<<<dim3(4, 128, 32), 256>>>(pC2, 28 * 28);
    }
    // ---- conv3 (128->256, 28->14) ----
    {
        int smem = (4 * 128 * 9 + 4 * 28 * 28) * 4;
        conv3x3s2_k<128, 28, 14, 4, 4, 224, 1><<<dim3(256 / 4, 32 / 4), 224, smem>>>(pC2, w3, pC3, 256);
        bn_stats_k<<<256, 256>>>(pC3, g3, be3, 256, 14 * 14);
        bn_relu_k<<<dim3(1, 256, 32), 256>>>(pC3, 14 * 14);
    }
    // ---- conv4 (256->512, 14->7) ----
    {
        int smem = (4 * 256 * 9 + 8 * 7 * 7 * 4) * 4;
        conv3x3s2_k<256, 14, 7, 4, 8, 64, 1><<<dim3(512 / 4, 32 / 8), 64, smem>>>(pC3, w4, pC4, 512);
        bn_stats_k<<<512, 256>>>(pC4, g4, be4, 512, 7 * 7);
        bn_relu_k<<<dim3(1, 512, 32), 256>>>(pC4, 7 * 7);
    }

    // ---- head ----
    avgpool_k<<<32, 512>>>();
    enc_k<<<32, 512>>>(pw, pb);
    h0c0_k<<<32, 512>>>(ihw, ihb, icw, icb);

    // ---- LSTM: hoisted input GEMM, then 20 recurrent steps ----
    xgather_k<<<640, 512>>>(emb, caps);
    gemm128_k<1><<<dim3(2048 / 128, 640 / 64), 256>>>(pXs, wih, nullptr, pGx, 640, 2048, 512);
    for (int t = 0; t < 20; t++) {
        gemm_h_k<<<32, 128>>>(whh);
        lstm_point_k<<<64, 256>>>(bih, bhh, t);
    }

    // ---- logits: [640,512] @ [512,32000] + ob ----
    gemm128_k<0><<<dim3(32000 / 128, 640 / 64), 256>>>(pHs, ow, ob, (float*)d_out, 640, 32000, 512);
}

// round 2
// speedup vs baseline: 1.8404x; 1.8404x over previous
#include <cuda_runtime.h>
#include <math.h>

#define CK __restrict__

// ---------------- scratch ----------------
__device__ float g_c1[32 * 64 * 112 * 112];
__device__ float g_pool[32 * 64 * 56 * 56];
__device__ float g_c2[32 * 128 * 28 * 28];
__device__ float g_c3[32 * 256 * 14 * 14];
__device__ float g_c4[32 * 512 * 7 * 7];
__device__ float g_scale[960];   // L1@0(64) L2@64(128) L3@192(256) L4@448(512)
__device__ float g_shift[960];
__device__ float g_pa[512 * 16];
__device__ float g_pb[512 * 16];
__device__ float g_feats[32 * 512];
__device__ float g_enc[32 * 512];
__device__ float g_h[32 * 512];
__device__ float g_cst[32 * 512];
__device__ float g_xs[640 * 512];
__device__ float g_gx[640 * 2048];
__device__ float g_hs[640 * 512];
__device__ float g_bsum[2048];
__device__ int g_count;
__device__ int g_gen;

// ---------------- tiny init / prep kernels ----------------
__global__ void init_k() { if (threadIdx.x == 0) { g_count = 0; g_gen = 0; } }

__global__ void biassum_k(const float* CK bih, const float* CK bhh) {
    int i = blockIdx.x * 256 + threadIdx.x;
    if (i < 2048) g_bsum[i] = bih[i] + bhh[i];
}

__global__ void xgather_k(const float* CK emb, const int* CK caps) {
    int m = blockIdx.x;
    int b = m / 20, t = m - b * 20;
    int tok = caps[b * 21 + t];
    g_xs[m * 512 + threadIdx.x] = emb[(size_t)tok * 512 + threadIdx.x];
}

// ---------------- conv1: 7x7 s2 p3, 3->64, 8 co per block ----------------
// grid (28, 8, 32), block 112
__global__ void conv1_k(const float* CK img, const float* CK w) {
    const int y0  = blockIdx.x * 4;
    const int co0 = blockIdx.y * 8;
    const int n   = blockIdx.z;
    const int x   = threadIdx.x;
    __shared__ float ws[8 * 147];
    __shared__ __align__(16) float srow[39][232];  // parity-deinterleaved

    for (int i = x; i < 8 * 147; i += 112) {
        int t = i / 147, r = i - t * 147;
        ws[i] = w[(co0 + t) * 147 + r];
    }
    for (int r = 0; r < 39; r++) {
        int ci = r / 13, d = r - ci * 13;
        int iy = y0 * 2 - 3 + d;
        const float* src = img + ((n * 3 + ci) * 224 + iy) * 224;
        bool ok = (iy >= 0 && iy < 224);
        for (int c = x; c < 232; c += 112) {
            int xm = c - 3;
            float v = (ok && xm >= 0 && xm < 224) ? src[xm] : 0.f;
            srow[r][(c >> 1) + (c & 1) * 116] = v;
        }
    }
    __syncthreads();

    float acc[8][4];
#pragma unroll
    for (int c = 0; c < 8; c++)
#pragma unroll
        for (int r = 0; r < 4; r++) acc[c][r] = 0.f;

#pragma unroll
    for (int ci = 0; ci < 3; ci++) {
#pragma unroll
        for (int ky = 0; ky < 7; ky++) {
#pragma unroll
            for (int kx = 0; kx < 7; kx++) {
                int col = 2 * x + kx;
                int a = (col >> 1) + (col & 1) * 116;
                int rb = ci * 13 + ky;
                float v0 = srow[rb][a], v1 = srow[rb + 2][a];
                float v2 = srow[rb + 4][a], v3 = srow[rb + 6][a];
                int wi = ci * 49 + ky * 7 + kx;
#pragma unroll
                for (int c = 0; c < 8; c++) {
                    float wv = ws[c * 147 + wi];
                    acc[c][0] += v0 * wv; acc[c][1] += v1 * wv;
                    acc[c][2] += v2 * wv; acc[c][3] += v3 * wv;
                }
            }
        }
    }
#pragma unroll
    for (int c = 0; c < 8; c++)
#pragma unroll
        for (int r = 0; r < 4; r++)
            g_c1[((size_t)(n * 64 + co0 + c) * 112 + y0 + r) * 112 + x] = acc[c][r];
}

// ---------------- BN: split-N partial sums (deterministic) ----------------
__global__ void bn_part_k(const float* CK x, int C, int HW, int NPR) {
    int c = blockIdx.x, s = blockIdx.y, tid = threadIdx.x;
    float a = 0.f, b = 0.f;
    for (int n = s * NPR; n < (s + 1) * NPR; n++) {
        const float* p = x + (size_t)(n * C + c) * HW;
        for (int i = tid; i < HW; i += 256) { float v = p[i]; a += v; b += v * v; }
    }
    __shared__ float sa[256], sb[256];
    sa[tid] = a; sb[tid] = b;
    __syncthreads();
    for (int st = 128; st > 0; st >>= 1) {
        if (tid < st) { sa[tid] += sa[tid + st]; sb[tid] += sb[tid + st]; }
        __syncthreads();
    }
    if (tid == 0) { g_pa[c * gridDim.y + s] = sa[0]; g_pb[c * gridDim.y + s] = sb[0]; }
}

__global__ void bn_fin_k(const float* CK g, const float* CK be, int C, int S,
                         float invN, int base) {
    int c = blockIdx.x * 64 + threadIdx.x;
    if (c >= C) return;
    float a = 0.f, b = 0.f;
    for (int s = 0; s < S; s++) { a += g_pa[c * S + s]; b += g_pb[c * S + s]; }
    float m = a * invN;
    float var = b * invN - m * m;
    float sc = g[c] * rsqrtf(var + 1e-5f);
    g_scale[base + c] = sc;
    g_shift[base + c] = be[c] - m * sc;
}

// ---------------- maxpool fused with BN1+ReLU ----------------
__global__ void pool_k() {
    int c = blockIdx.y, n = blockIdx.z;
    int p = blockIdx.x * 256 + threadIdx.x;
    if (p >= 56 * 56) return;
    int oy = p / 56, ox = p - oy * 56;
    const float* src = g_c1 + (size_t)((n * 64 + c) * 112) * 112;
    float m = -1e30f;
    int iy0 = oy * 2 - 1, ix0 = ox * 2 - 1;
#pragma unroll
    for (int dy = 0; dy < 3; dy++) {
        int iy = iy0 + dy;
        if (iy < 0 || iy >= 112) continue;
#pragma unroll
        for (int dx = 0; dx < 3; dx++) {
            int ix = ix0 + dx;
            if (ix < 0 || ix >= 112) continue;
            float v = src[iy * 112 + ix];
            m = v > m ? v : m;
        }
    }
    float r = m * g_scale[c] + g_shift[c];   // scale>0 so max commutes with affine
    g_pool[((n * 64 + c) * 56 + oy) * 56 + ox] = r > 0.f ? r : 0.f;
}

// ---------------- generic 3x3 s2 p1 conv, TCO=8, optional input BN+ReLU ----------------
template <int CIN, int HIN, int HOUT, int TCO, int TN, int NT, int P, bool APPLY>
__global__ void conv3x3s2_k(const float* CK in, const float* CK w, float* CK out,
                            int COUT, int cbase) {
    const int HIN2 = HIN * HIN, HOUT2 = HOUT * HOUT, HALF = HIN / 2;
    extern __shared__ float sm[];
    float* ws = sm;                       // TCO*CIN*9
    float* pl = sm + TCO * CIN * 9;       // TN * HIN2
    int tid = threadIdx.x;
    int co0 = blockIdx.x * TCO;
    int n0  = blockIdx.y * TN;

    for (int i = tid; i < TCO * CIN * 9; i += NT) {
        int t = i / (CIN * 9), r = i - t * (CIN * 9);
        ws[i] = w[(size_t)(co0 + t) * CIN * 9 + r];
    }

    int adr[P][9];
#pragma unroll
    for (int p = 0; p < P; p++) {
        int q = tid + p * NT;
        bool v = q < HOUT2;
        int oy = v ? q / HOUT : 0;
        int ox = v ? q - oy * HOUT : 0;
#pragma unroll
        for (int ky = 0; ky < 3; ky++)
#pragma unroll
            for (int kx = 0; kx < 3; kx++) {
                int iy = oy * 2 - 1 + ky;
                int ix = ox * 2 - 1 + kx;
                bool inb = v && iy >= 0 && iy < HIN && ix >= 0 && ix < HIN;
                adr[p][ky * 3 + kx] = inb ? iy * HIN + (ix >> 1) + (ix & 1) * HALF : -1;
            }
    }

    float acc[TCO][TN][P];
#pragma unroll
    for (int t = 0; t < TCO; t++)
#pragma unroll
        for (int tn = 0; tn < TN; tn++)
#pragma unroll
            for (int p = 0; p < P; p++) acc[t][tn][p] = 0.f;

    for (int ci = 0; ci < CIN; ci++) {
        float scv = 0.f, shv = 0.f;
        if (APPLY) { scv = g_scale[cbase + ci]; shv = g_shift[cbase + ci]; }
        __syncthreads();
        for (int i = tid; i < TN * HIN2; i += NT) {
            int tn = i / HIN2, r = i - tn * HIN2;
            int iy = r / HIN, ix = r - iy * HIN;
            float v = in[((size_t)(n0 + tn) * CIN + ci) * HIN2 + r];
            if (APPLY) { v = v * scv + shv; v = v > 0.f ? v : 0.f; }
            pl[tn * HIN2 + iy * HIN + (ix >> 1) + (ix & 1) * HALF] = v;
        }
        __syncthreads();
#pragma unroll
        for (int tap = 0; tap < 9; tap++) {
            float wv[TCO];
#pragma unroll
            for (int t = 0; t < TCO; t++) wv[t] = ws[t * CIN * 9 + ci * 9 + tap];
#pragma unroll
            for (int p = 0; p < P; p++) {
                int a = adr[p][tap];
                if (a >= 0) {
#pragma unroll
                    for (int tn = 0; tn < TN; tn++) {
                        float v = pl[tn * HIN2 + a];
#pragma unroll
                        for (int t = 0; t < TCO; t++) acc[t][tn][p] += v * wv[t];
                    }
                }
            }
        }
    }

#pragma unroll
    for (int p = 0; p < P; p++) {
        int q = tid + p * NT;
        if (q < HOUT2) {
#pragma unroll
            for (int tn = 0; tn < TN; tn++)
#pragma unroll
                for (int t = 0; t < TCO; t++)
                    out[((size_t)(n0 + tn) * COUT + co0 + t) * HOUT2 + q] = acc[t][tn][p];
        }
    }
}

// ---------------- avgpool fused with BN4+ReLU ----------------
__global__ void avgpool_k() {
    int n = blockIdx.x, c = threadIdx.x;
    float sc = g_scale[448 + c], sh = g_shift[448 + c];
    const float* p = g_c4 + (size_t)(n * 512 + c) * 49;
    float s = 0.f;
#pragma unroll
    for (int i = 0; i < 49; i++) { float v = p[i] * sc + sh; s += v > 0.f ? v : 0.f; }
    g_feats[n * 512 + c] = s * (1.f / 49.f);
}

__global__ void enc_k(const float* CK pw, const float* CK pb) {
    int n = blockIdx.x, o = threadIdx.x;
    __shared__ float fr[512];
    fr[o] = g_feats[n * 512 + o];
    __syncthreads();
    float acc = pb[o];
    for (int k = 0; k < 512; k++) acc += fr[k] * pw[k * 512 + o];
    g_enc[n * 512 + o] = acc;
}

__global__ void h0c0_k(const float* CK ihw, const float* CK ihb,
                       const float* CK icw, const float* CK icb) {
    int n = blockIdx.x, o = threadIdx.x;
    __shared__ float er[512];
    er[o] = g_enc[n * 512 + o];
    __syncthreads();
    float ah = ihb[o], ac = icb[o];
    for (int k = 0; k < 512; k++) {
        float e = er[k];
        ah += e * ihw[k * 512 + o];
        ac += e * icw[k * 512 + o];
    }
    g_h[n * 512 + o]   = tanhf(ah);
    g_cst[n * 512 + o] = tanhf(ac);
}

// ---------------- SGEMM 64x128x16 (used for gates_x) ----------------
template <int TRANSB>
__global__ void gemm128_k(const float* CK A, const float* CK Bm, const float* CK bias,
                          float* CK Cm, int M, int N, int K) {
    __shared__ __align__(16) float As[16][64];
    __shared__ __align__(16) float Bs[16][128];
    int tid = threadIdx.x;
    int n0 = blockIdx.x * 128;
    int m0 = blockIdx.y * 64;
    int tx = tid & 15, ty = tid >> 4;
    float acc[4][8];
#pragma unroll
    for (int i = 0; i < 4; i++)
#pragma unroll
        for (int j = 0; j < 8; j++) acc[i][j] = 0.f;

    int ar = tid >> 2, aq = (tid & 3) * 4;
    for (int k0 = 0; k0 < K; k0 += 16) {
        float4 av = *(const float4*)(A + (size_t)(m0 + ar) * K + k0 + aq);
        As[aq + 0][ar] = av.x; As[aq + 1][ar] = av.y;
        As[aq + 2][ar] = av.z; As[aq + 3][ar] = av.w;
        if (TRANSB) {
            int bn = tid >> 1, bq = (tid & 1) * 8;
            float4 b0 = *(const float4*)(Bm + (size_t)(n0 + bn) * K + k0 + bq);
            float4 b1 = *(const float4*)(Bm + (size_t)(n0 + bn) * K + k0 + bq + 4);
            Bs[bq + 0][bn] = b0.x; Bs[bq + 1][bn] = b0.y; Bs[bq + 2][bn] = b0.z; Bs[bq + 3][bn] = b0.w;
            Bs[bq + 4][bn] = b1.x; Bs[bq + 5][bn] = b1.y; Bs[bq + 6][bn] = b1.z; Bs[bq + 7][bn] = b1.w;
        } else {
            int br = tid >> 4, bc = (tid & 15) * 8;
            *(float4*)&Bs[br][bc]     = *(const float4*)(Bm + (size_t)(k0 + br) * N + n0 + bc);
            *(float4*)&Bs[br][bc + 4] = *(const float4*)(Bm + (size_t)(k0 + br) * N + n0 + bc + 4);
        }
        __syncthreads();
#pragma unroll
        for (int k = 0; k < 16; k++) {
            float4 a4 = *(const float4*)&As[k][ty * 4];
            float4 b4 = *(const float4*)&Bs[k][tx * 8];
            float4 b5 = *(const float4*)&Bs[k][tx * 8 + 4];
            float aa[4] = {a4.x, a4.y, a4.z, a4.w};
            float bb[8] = {b4.x, b4.y, b4.z, b4.w, b5.x, b5.y, b5.z, b5.w};
#pragma unroll
            for (int i = 0; i < 4; i++)
#pragma unroll
                for (int j = 0; j < 8; j++) acc[i][j] += aa[i] * bb[j];
        }
        __syncthreads();
    }
#pragma unroll
    for (int i = 0; i < 4; i++) {
        float* crow = Cm + (size_t)(m0 + ty * 4 + i) * N + n0 + tx * 8;
#pragma unroll
        for (int j = 0; j < 8; j++) {
            float v = acc[i][j];
            if (bias) v += bias[n0 + tx * 8 + j];
            crow[j] = v;
        }
    }
}

// ---------------- big SGEMM 128x128x16, 8x8 frags, reg-staged prefetch ----------------
__global__ void gemm_big_k(const float* CK A, const float* CK B, const float* CK bias,
                           float* CK C, int N, int K) {
    __shared__ __align__(16) float As[16][128];
    __shared__ __align__(16) float Bs[16][128];
    int tid = threadIdx.x;
    int n0 = blockIdx.x * 128, m0 = blockIdx.y * 128;
    int ar = tid >> 1, aq = (tid & 1) * 8;
    int br = tid >> 4, bc = (tid & 15) * 8;
    int tx = tid & 15, ty = tid >> 4;
    float acc[8][8];
#pragma unroll
    for (int i = 0; i < 8; i++)
#pragma unroll
        for (int j = 0; j < 8; j++) acc[i][j] = 0.f;

    const float* Ap = A + (size_t)(m0 + ar) * K + aq;
    const float* Bp = B + (size_t)br * N + n0 + bc;
    float4 a0 = *(const float4*)(Ap);
    float4 a1 = *(const float4*)(Ap + 4);
    float4 b0 = *(const float4*)(Bp);
    float4 b1 = *(const float4*)(Bp + 4);

    int k0 = 0;
    for (;;) {
        As[aq + 0][ar] = a0.x; As[aq + 1][ar] = a0.y; As[aq + 2][ar] = a0.z; As[aq + 3][ar] = a0.w;
        As[aq + 4][ar] = a1.x; As[aq + 5][ar] = a1.y; As[aq + 6][ar] = a1.z; As[aq + 7][ar] = a1.w;
        *(float4*)&Bs[br][bc]     = b0;
        *(float4*)&Bs[br][bc + 4] = b1;
        __syncthreads();
        k0 += 16;
        bool more = k0 < K;
        if (more) {
            a0 = *(const float4*)(Ap + k0);
            a1 = *(const float4*)(Ap + k0 + 4);
            b0 = *(const float4*)(Bp + (size_t)k0 * N);
            b1 = *(const float4*)(Bp + (size_t)k0 * N + 4);
        }
#pragma unroll
        for (int k = 0; k < 16; k++) {
            float av[8], bv[8];
            *(float4*)(av)     = *(const float4*)&As[k][ty * 8];
            *(float4*)(av + 4) = *(const float4*)&As[k][ty * 8 + 4];
            *(float4*)(bv)     = *(const float4*)&Bs[k][tx * 8];
            *(float4*)(bv + 4) = *(const float4*)&Bs[k][tx * 8 + 4];
#pragma unroll
            for (int i = 0; i < 8; i++)
#pragma unroll
                for (int j = 0; j < 8; j++) acc[i][j] += av[i] * bv[j];
        }
        if (!more) break;
        __syncthreads();
    }
#pragma unroll
    for (int i = 0; i < 8; i++) {
        float* crow = C + (size_t)(m0 + ty * 8 + i) * N + n0 + tx * 8;
#pragma unroll
        for (int j = 0; j < 8; j++) crow[j] = acc[i][j] + bias[n0 + tx * 8 + j];
    }
}

// ---------------- persistent LSTM: 64 blocks x 256 threads ----------------
__device__ __forceinline__ float sigf(float x) { return 1.f / (1.f + expf(-x)); }

#define LSTM_NBLK 64
#define WP 516   // pitch in floats (odd in 16B units -> conflict-free stride-1 rows)

__global__ void lstm_k(const float* CK whh) {
    extern __shared__ float sm[];
    float* wsm = sm;                      // 32 rows x WP
    float* hbf = sm + 32 * WP;            // 32 batches x WP
    float* gsm = hbf + 32 * WP;           // 2 x 32 x 33
    __shared__ float bsum_s[32];

    const int tid = threadIdx.x;
    const int jb = blockIdx.x * 8;

    // weights: row r = gate*8 + jj  ->  whh row gate*512 + jb + jj
    for (int i = tid; i < 32 * 128; i += 256) {
        int r = i >> 7, k4 = i & 127;
        int row = ((r >> 3) * 512) + jb + (r & 7);
        *((float4*)(wsm + r * WP) + k4) = *((const float4*)(whh + (size_t)row * 512) + k4);
    }
    if (tid < 32) bsum_s[tid] = g_bsum[((tid >> 3) * 512) + jb + (tid & 7)];

    const int b_own = tid >> 3, j_own = tid & 7;
    float c = g_cst[b_own * 512 + jb + j_own];

    // initial h
    for (int i = tid; i < 32 * 128; i += 256) {
        int b = i >> 7, k4 = i & 127;
        *((float4*)(hbf + b * WP) + k4) = __ldcg((const float4*)(g_h + b * 512) + k4);
    }
    __syncthreads();

    const int half = tid >> 7;
    const int tt = tid & 127;
    const int r0 = tt & 15;
    const int b0 = (tt >> 4) * 4;
    const int kb = half * 64;   // float4 offset

    const float4* wA = (const float4*)(wsm + r0 * WP) + kb;
    const float4* wB = (const float4*)(wsm + (r0 + 16) * WP) + kb;

    for (int t = 0; t < 20; t++) {
        // ---- gemm: gates_h[r][b], K split by half ----
        float a0[4] = {0.f, 0.f, 0.f, 0.f};
        float a1[4] = {0.f, 0.f, 0.f, 0.f};
        const float4* h0 = (const float4*)(hbf + (b0 + 0) * WP) + kb;
        const float4* h1 = (const float4*)(hbf + (b0 + 1) * WP) + kb;
        const float4* h2 = (const float4*)(hbf + (b0 + 2) * WP) + kb;
        const float4* h3 = (const float4*)(hbf + (b0 + 3) * WP) + kb;
#pragma unroll 8
        for (int k = 0; k < 64; k++) {
            float4 w0 = wA[k], w1 = wB[k];
            float4 hv;
            hv = h0[k];
            a0[0] += w0.x * hv.x + w0.y * hv.y + w0.z * hv.z + w0.w * hv.w;
            a1[0] += w1.x * hv.x + w1.y * hv.y + w1.z * hv.z + w1.w * hv.w;
            hv = h1[k];
            a0[1] += w0.x * hv.x + w0.y * hv.y + w0.z * hv.z + w0.w * hv.w;
            a1[1] += w1.x * hv.x + w1.y * hv.y + w1.z * hv.z + w1.w * hv.w;
            hv = h2[k];
            a0[2] += w0.x * hv.x + w0.y * hv.y + w0.z * hv.z + w0.w * hv.w;
            a1[2] += w1.x * hv.x + w1.y * hv.y + w1.z * hv.z + w1.w * hv.w;
            hv = h3[k];
            a0[3] += w0.x * hv.x + w0.y * hv.y + w0.z * hv.z + w0.w * hv.w;
            a1[3] += w1.x * hv.x + w1.y * hv.y + w1.z * hv.z + w1.w * hv.w;
        }
#pragma unroll
        for (int j = 0; j < 4; j++) {
            gsm[half * 1056 + r0 * 33 + b0 + j]        = a0[j];
            gsm[half * 1056 + (r0 + 16) * 33 + b0 + j] = a1[j];
        }
        __syncthreads();

        // ---- pointwise ----
        const int m = b_own * 20 + t;
        const float* gxp = g_gx + (size_t)m * 2048 + jb + j_own;
        float iv = gsm[j_own * 33 + b_own]        + gsm[1056 + j_own * 33 + b_own]        + gxp[0]    + bsum_s[j_own];
        float fv = gsm[(8 + j_own) * 33 + b_own]  + gsm[1056 + (8 + j_own) * 33 + b_own]  + gxp[512]  + bsum_s[8 + j_own];
        float gv = gsm[(16 + j_own) * 33 + b_own] + gsm[1056 + (16 + j_own) * 33 + b_own] + gxp[1024] + bsum_s[16 + j_own];
        float ov = gsm[(24 + j_own) * 33 + b_own] + gsm[1056 + (24 + j_own) * 33 + b_own] + gxp[1536] + bsum_s[24 + j_own];
        c = sigf(fv) * c + sigf(iv) * tanhf(gv);
        float h = sigf(ov) * tanhf(c);
        g_h[b_own * 512 + jb + j_own] = h;
        g_hs[(size_t)m * 512 + jb + j_own] = h;

        // ---- grid barrier ----
        __syncthreads();
        if (tid == 0) {
            __threadfence();
            if (atomicAdd(&g_count, 1) == LSTM_NBLK - 1) {
                g_count = 0;
                __threadfence();
                atomicExch(&g_gen, t + 1);
            } else {
                while (((volatile int*)&g_gen)[0] < t + 1) {}
                __threadfence();
            }
        }
        __syncthreads();

        // ---- reload full h ----
        for (int i = tid; i < 32 * 128; i += 256) {
            int b = i >> 7, k4 = i & 127;
            *((float4*)(hbf + b * WP) + k4) = __ldcg((const float4*)(g_h + b * 512) + k4);
        }
        __syncthreads();
    }
}

// ---------------- launch ----------------
extern "C" void kernel_launch(void* const* d_in, const int* in_sizes, int n_in,
                              void* d_out, int out_size) {
    const float* images = (const float*)d_in[0];
    const int*   caps   = (const int*)d_in[1];
    const float* w1  = (const float*)d_in[2];
    const float* g1  = (const float*)d_in[3];
    const float* be1 = (const float*)d_in[4];
    const float* w2  = (const float*)d_in[5];
    const float* g2  = (const float*)d_in[6];
    const float* be2 = (const float*)d_in[7];
    const float* w3  = (const float*)d_in[8];
    const float* g3  = (const float*)d_in[9];
    const float* be3 = (const float*)d_in[10];
    const float* w4  = (const float*)d_in[11];
    const float* g4  = (const float*)d_in[12];
    const float* be4 = (const float*)d_in[13];
    const float* pw  = (const float*)d_in[14];
    const float* pb  = (const float*)d_in[15];
    const float* emb = (const float*)d_in[16];
    const float* ihw = (const float*)d_in[17];
    const float* ihb = (const float*)d_in[18];
    const float* icw = (const float*)d_in[19];
    const float* icb = (const float*)d_in[20];
    const float* wih = (const float*)d_in[21];
    const float* whh = (const float*)d_in[22];
    const float* bih = (const float*)d_in[23];
    const float* bhh = (const float*)d_in[24];
    const float* ow  = (const float*)d_in[25];
    const float* ob  = (const float*)d_in[26];

    float *pC1, *pPool, *pC2, *pC3, *pC4, *pXs, *pGx, *pHs;
    cudaGetSymbolAddress((void**)&pC1, g_c1);
    cudaGetSymbolAddress((void**)&pPool, g_pool);
    cudaGetSymbolAddress((void**)&pC2, g_c2);
    cudaGetSymbolAddress((void**)&pC3, g_c3);
    cudaGetSymbolAddress((void**)&pC4, g_c4);
    cudaGetSymbolAddress((void**)&pXs, g_xs);
    cudaGetSymbolAddress((void**)&pGx, g_gx);
    cudaGetSymbolAddress((void**)&pHs, g_hs);

    const int smem2 = (8 * 64 * 9 + 56 * 56) * 4;                 // 30976
    const int smem3 = (8 * 128 * 9 + 4 * 28 * 28) * 4;            // 49408
    const int smem4 = (8 * 256 * 9 + 8 * 14 * 14) * 4;            // 80000
    const int smemL = (32 * WP + 32 * WP + 2 * 32 * 33) * 4;      // 140544
    cudaFuncSetAttribute(conv3x3s2_k<128, 28, 14, 8, 4, 224, 1, true>,
                         cudaFuncAttributeMaxDynamicSharedMemorySize, smem3);
    cudaFuncSetAttribute(conv3x3s2_k<256, 14, 7, 8, 8, 64, 1, true>,
                         cudaFuncAttributeMaxDynamicSharedMemorySize, smem4);
    cudaFuncSetAttribute(lstm_k, cudaFuncAttributeMaxDynamicSharedMemorySize, smemL);

    // 5 dependency-free launches first => ncu (-s 5 -c 1) profiles conv1_k
    init_k<<<1, 32>>>();                                              // 0
    biassum_k<<<8, 256>>>(bih, bhh);                                  // 1
    xgather_k<<<640, 512>>>(emb, caps);                               // 2
    gemm128_k<1><<<dim3(8, 10), 256>>>(pXs, wih, nullptr, pGx,        // 3
                                       640, 2048, 512);
    gemm128_k<1><<<dim3(8, 10), 256>>>(pXs, wih + 1024 * 512, nullptr,// 4
                                       pGx + 1024, 640, 2048, 512);

    conv1_k<<<dim3(28, 8, 32), 112>>>(images, w1);                    // 5 (profiled)
    bn_part_k<<<dim3(64, 16), 256>>>(pC1, 64, 112 * 112, 2);
    bn_fin_k<<<1, 64>>>(g1, be1, 64, 16, 1.f / (32.f * 112 * 112), 0);
    pool_k<<<dim3(13, 64, 32), 256>>>();

    conv3x3s2_k<64, 56, 28, 8, 1, 256, 4, false>
        <<<dim3(16, 32), 256, smem2>>>(pPool, w2, pC2, 128, 0);
    bn_part_k<<<dim3(128, 8), 256>>>(pC2, 128, 28 * 28, 4);
    bn_fin_k<<<2, 64>>>(g2, be2, 128, 8, 1.f / (32.f * 28 * 28), 64);

    conv3x3s2_k<128, 28, 14, 8, 4, 224, 1, true>
        <<<dim3(32, 8), 224, smem3>>>(pC2, w3, pC3, 256, 64);
    bn_part_k<<<dim3(256, 4), 256>>>(pC3, 256, 14 * 14, 8);
    bn_fin_k<<<4, 64>>>(g3, be3, 256, 4, 1.f / (32.f * 14 * 14), 192);

    conv3x3s2_k<256, 14, 7, 8, 8, 64, 1, true>
        <<<dim3(64, 4), 64, smem4>>>(pC3, w4, pC4, 512, 192);
    bn_part_k<<<dim3(512, 2), 256>>>(pC4, 512, 7 * 7, 16);
    bn_fin_k<<<8, 64>>>(g4, be4, 512, 2, 1.f / (32.f * 7 * 7), 448);

    avgpool_k<<<32, 512>>>();
    enc_k<<<32, 512>>>(pw, pb);
    h0c0_k<<<32, 512>>>(ihw, ihb, icw, icb);

    lstm_k<<<LSTM_NBLK, 256, smemL>>>(whh);

    gemm_big_k<<<dim3(250, 5), 256>>>(pHs, ow, ob, (float*)d_out, 32000, 512);
}

// round 5
// speedup vs baseline: 1.9307x; 1.0491x over previous
#include <cuda_runtime.h>
#include <mma.h>
#include <math.h>

#define CK __restrict__
using namespace nvcuda;

// ---------------- scratch ----------------
__device__ float g_c1[32 * 64 * 112 * 112];
__device__ float g_pool[32 * 64 * 56 * 56];
__device__ float g_c2[32 * 128 * 28 * 28];
__device__ float g_c3[32 * 256 * 14 * 14];
__device__ float g_c4[32 * 512 * 7 * 7];
__device__ float g_wihT[512 * 2048];
__device__ float g_scale[960];
__device__ float g_shift[960];
__device__ float g_pa[512 * 16];
__device__ float g_pb[512 * 16];
__device__ float g_feats[32 * 512];
__device__ float g_enc[32 * 512];
__device__ float g_h[32 * 512];
__device__ float g_cst[32 * 512];
__device__ float g_xs[640 * 512];
__device__ float g_gx[640 * 2048];
__device__ float g_hs[640 * 512];
__device__ float g_bsum[2048];
__device__ int g_count;
__device__ int g_gen;

// ---------------- tiny init / prep ----------------
__global__ void init_k() { if (threadIdx.x == 0) { g_count = 0; g_gen = 0; } }

__global__ void biassum_k(const float* CK bih, const float* CK bhh) {
    int i = blockIdx.x * 256 + threadIdx.x;
    if (i < 2048) g_bsum[i] = bih[i] + bhh[i];
}

__global__ void xgather_k(const float* CK emb, const int* CK caps) {
    int m = blockIdx.x;
    int b = m / 20, t = m - b * 20;
    int tok = caps[b * 21 + t];
    g_xs[m * 512 + threadIdx.x] = emb[(size_t)tok * 512 + threadIdx.x];
}

// wih [2048,512] -> g_wihT [512,2048]
__global__ void wihT_k(const float* CK w) {
    __shared__ float t[32][33];
    int bx = blockIdx.x * 32, by = blockIdx.y * 32;
    int tx = threadIdx.x & 31, ty = threadIdx.x >> 5;
    for (int i = ty; i < 32; i += 8)
        t[i][tx] = w[(size_t)(by + i) * 512 + bx + tx];
    __syncthreads();
    for (int i = ty; i < 32; i += 8)
        g_wihT[(size_t)(bx + i) * 2048 + by + tx] = t[tx][i];
}

// ---------------- TF32 WMMA GEMM: C[M,N] = A[M,K] @ B[K,N] (+bias) ----------------
// BM=128 BN=128 BK=32, 256 threads, 8 warps (2x4), warp tile 64x32 (4x2 m16n16k8).
__global__ void gemm_wmma_k(const float* CK A, const float* CK B, const float* CK bias,
                            float* CK C, int M, int N, int K) {
    __shared__ __align__(32) float As[32][136];   // [k][m]  (col-major A tiles)
    __shared__ __align__(32) float Bs[32][136];   // [k][n]  (row-major B tiles)
    const int tid = threadIdx.x;
    const int warp = tid >> 5, lane = tid & 31;
    const int m0 = blockIdx.y * 128, n0 = blockIdx.x * 128;
    const int wm = (warp >> 2) * 64, wn = (warp & 3) * 32;

    wmma::fragment<wmma::accumulator, 16, 16, 8, float> acc[4][2];
#pragma unroll
    for (int mf = 0; mf < 4; mf++)
#pragma unroll
        for (int nf = 0; nf < 2; nf++) wmma::fill_fragment(acc[mf][nf], 0.f);

    const int am = tid >> 1, ak = (tid & 1) * 16;
    const int bk = tid >> 3, bn = (tid & 7) * 16;
    const float* Ap = A + (size_t)(m0 + am) * K + ak;
    const float* Bp = B + (size_t)bk * N + n0 + bn;

    for (int k0 = 0; k0 < K; k0 += 32) {
#pragma unroll
        for (int i = 0; i < 4; i++) {
            float4 v = *(const float4*)(Ap + k0 + i * 4);
            As[ak + i * 4 + 0][am] = wmma::__float_to_tf32(v.x);
            As[ak + i * 4 + 1][am] = wmma::__float_to_tf32(v.y);
            As[ak + i * 4 + 2][am] = wmma::__float_to_tf32(v.z);
            As[ak + i * 4 + 3][am] = wmma::__float_to_tf32(v.w);
        }
#pragma unroll
        for (int i = 0; i < 4; i++) {
            float4 v = *(const float4*)(Bp + (size_t)k0 * N + i * 4);
            Bs[bk][bn + i * 4 + 0] = wmma::__float_to_tf32(v.x);
            Bs[bk][bn + i * 4 + 1] = wmma::__float_to_tf32(v.y);
            Bs[bk][bn + i * 4 + 2] = wmma::__float_to_tf32(v.z);
            Bs[bk][bn + i * 4 + 3] = wmma::__float_to_tf32(v.w);
        }
        __syncthreads();
#pragma unroll
        for (int ks = 0; ks < 4; ks++) {
            wmma::fragment<wmma::matrix_a, 16, 16, 8, wmma::precision::tf32,
                           wmma::col_major> af[4];
            wmma::fragment<wmma::matrix_b, 16, 16, 8, wmma::precision::tf32,
                           wmma::row_major> bf[2];
#pragma unroll
            for (int mf = 0; mf < 4; mf++)
                wmma::load_matrix_sync(af[mf], &As[ks * 8][wm + mf * 16], 136);
#pragma unroll
            for (int nf = 0; nf < 2; nf++)
                wmma::load_matrix_sync(bf[nf], &Bs[ks * 8][wn + nf * 16], 136);
#pragma unroll
            for (int mf = 0; mf < 4; mf++)
#pragma unroll
                for (int nf = 0; nf < 2; nf++)
                    wmma::mma_sync(acc[mf][nf], af[mf], bf[nf], acc[mf][nf]);
        }
        __syncthreads();
    }

    // epilogue: per-warp private smem buffer (reuses As region), bias add, float4 out
    float* wb = &As[0][0] + warp * 320;   // 16x20 floats per warp, 32B-aligned
    const int er = lane >> 1, ec = (lane & 1) * 8;
#pragma unroll
    for (int mf = 0; mf < 4; mf++)
#pragma unroll
        for (int nf = 0; nf < 2; nf++) {
            wmma::store_matrix_sync(wb, acc[mf][nf], 20, wmma::mem_row_major);
            __syncwarp();
            int row = m0 + wm + mf * 16 + er;
            int col = n0 + wn + nf * 16 + ec;
            float out[8];
#pragma unroll
            for (int j = 0; j < 8; j++) {
                float bv = bias ? bias[col + j] : 0.f;
                out[j] = wb[er * 20 + ec + j] + bv;
            }
            *(float4*)(C + (size_t)row * N + col)     = *(float4*)(out);
            *(float4*)(C + (size_t)row * N + col + 4) = *(float4*)(out + 4);
            __syncwarp();
        }
}

// ---------------- conv1 ----------------
__global__ void conv1_k(const float* CK img, const float* CK w) {
    const int y0  = blockIdx.x * 4;
    const int co0 = blockIdx.y * 8;
    const int n   = blockIdx.z;
    const int x   = threadIdx.x;
    __shared__ float ws[8 * 147];
    __shared__ __align__(16) float srow[39][232];

    for (int i = x; i < 8 * 147; i += 112) {
        int t = i / 147, r = i - t * 147;
        ws[i] = w[(co0 + t) * 147 + r];
    }
    for (int r = 0; r < 39; r++) {
        int ci = r / 13, d = r - ci * 13;
        int iy = y0 * 2 - 3 + d;
        const float* src = img + ((n * 3 + ci) * 224 + iy) * 224;
        bool ok = (iy >= 0 && iy < 224);
        for (int c = x; c < 232; c += 112) {
            int xm = c - 3;
            float v = (ok && xm >= 0 && xm < 224) ? src[xm] : 0.f;
            srow[r][(c >> 1) + (c & 1) * 116] = v;
        }
    }
    __syncthreads();

    float acc[8][4];
#pragma unroll
    for (int c = 0; c < 8; c++)
#pragma unroll
        for (int r = 0; r < 4; r++) acc[c][r] = 0.f;

#pragma unroll
    for (int ci = 0; ci < 3; ci++)
#pragma unroll
        for (int ky = 0; ky < 7; ky++)
#pragma unroll
            for (int kx = 0; kx < 7; kx++) {
                int col = 2 * x + kx;
                int a = (col >> 1) + (col & 1) * 116;
                int rb = ci * 13 + ky;
                float v0 = srow[rb][a], v1 = srow[rb + 2][a];
                float v2 = srow[rb + 4][a], v3 = srow[rb + 6][a];
                int wi = ci * 49 + ky * 7 + kx;
#pragma unroll
                for (int c = 0; c < 8; c++) {
                    float wv = ws[c * 147 + wi];
                    acc[c][0] += v0 * wv; acc[c][1] += v1 * wv;
                    acc[c][2] += v2 * wv; acc[c][3] += v3 * wv;
                }
            }
#pragma unroll
    for (int c = 0; c < 8; c++)
#pragma unroll
        for (int r = 0; r < 4; r++)
            g_c1[((size_t)(n * 64 + co0 + c) * 112 + y0 + r) * 112 + x] = acc[c][r];
}

// ---------------- BN ----------------
__global__ void bn_part_k(const float* CK x, int C, int HW, int NPR) {
    int c = blockIdx.x, s = blockIdx.y, tid = threadIdx.x;
    float a = 0.f, b = 0.f;
    for (int n = s * NPR; n < (s + 1) * NPR; n++) {
        const float* p = x + (size_t)(n * C + c) * HW;
        for (int i = tid; i < HW; i += 256) { float v = p[i]; a += v; b += v * v; }
    }
    __shared__ float sa[256], sb[256];
    sa[tid] = a; sb[tid] = b;
    __syncthreads();
    for (int st = 128; st > 0; st >>= 1) {
        if (tid < st) { sa[tid] += sa[tid + st]; sb[tid] += sb[tid + st]; }
        __syncthreads();
    }
    if (tid == 0) { g_pa[c * gridDim.y + s] = sa[0]; g_pb[c * gridDim.y + s] = sb[0]; }
}

__global__ void bn_fin_k(const float* CK g, const float* CK be, int C, int S,
                         float invN, int base) {
    int c = blockIdx.x * 64 + threadIdx.x;
    if (c >= C) return;
    float a = 0.f, b = 0.f;
    for (int s = 0; s < S; s++) { a += g_pa[c * S + s]; b += g_pb[c * S + s]; }
    float m = a * invN;
    float var = b * invN - m * m;
    float sc = g[c] * rsqrtf(var + 1e-5f);
    g_scale[base + c] = sc;
    g_shift[base + c] = be[c] - m * sc;
}

// ---------------- maxpool fused BN1+ReLU ----------------
__global__ void pool_k() {
    int c = blockIdx.y, n = blockIdx.z;
    int p = blockIdx.x * 256 + threadIdx.x;
    if (p >= 56 * 56) return;
    int oy = p / 56, ox = p - oy * 56;
    const float* src = g_c1 + (size_t)((n * 64 + c) * 112) * 112;
    float m = -1e30f;
    int iy0 = oy * 2 - 1, ix0 = ox * 2 - 1;
#pragma unroll
    for (int dy = 0; dy < 3; dy++) {
        int iy = iy0 + dy;
        if (iy < 0 || iy >= 112) continue;
#pragma unroll
        for (int dx = 0; dx < 3; dx++) {
            int ix = ix0 + dx;
            if (ix < 0 || ix >= 112) continue;
            float v = src[iy * 112 + ix];
            m = v > m ? v : m;
        }
    }
    float r = m * g_scale[c] + g_shift[c];
    g_pool[((n * 64 + c) * 56 + oy) * 56 + ox] = r > 0.f ? r : 0.f;
}

// ---------------- generic 3x3 s2 conv ----------------
template <int CIN, int HIN, int HOUT, int TCO, int TN, int NT, int P, bool APPLY>
__global__ void conv3x3s2_k(const float* CK in, const float* CK w, float* CK out,
                            int COUT, int cbase) {
    const int HIN2 = HIN * HIN, HOUT2 = HOUT * HOUT, HALF = HIN / 2;
    extern __shared__ float sm[];
    float* ws = sm;
    float* pl = sm + TCO * CIN * 9;
    int tid = threadIdx.x;
    int co0 = blockIdx.x * TCO;
    int n0  = blockIdx.y * TN;

    for (int i = tid; i < TCO * CIN * 9; i += NT) {
        int t = i / (CIN * 9), r = i - t * (CIN * 9);
        ws[i] = w[(size_t)(co0 + t) * CIN * 9 + r];
    }

    int adr[P][9];
#pragma unroll
    for (int p = 0; p < P; p++) {
        int q = tid + p * NT;
        bool v = q < HOUT2;
        int oy = v ? q / HOUT : 0;
        int ox = v ? q - oy * HOUT : 0;
#pragma unroll
        for (int ky = 0; ky < 3; ky++)
#pragma unroll
            for (int kx = 0; kx < 3; kx++) {
                int iy = oy * 2 - 1 + ky;
                int ix = ox * 2 - 1 + kx;
                bool inb = v && iy >= 0 && iy < HIN && ix >= 0 && ix < HIN;
                adr[p][ky * 3 + kx] = inb ? iy * HIN + (ix >> 1) + (ix & 1) * HALF : -1;
            }
    }

    float acc[TCO][TN][P];
#pragma unroll
    for (int t = 0; t < TCO; t++)
#pragma unroll
        for (int tn = 0; tn < TN; tn++)
#pragma unroll
            for (int p = 0; p < P; p++) acc[t][tn][p] = 0.f;

    for (int ci = 0; ci < CIN; ci++) {
        float scv = 0.f, shv = 0.f;
        if (APPLY) { scv = g_scale[cbase + ci]; shv = g_shift[cbase + ci]; }
        __syncthreads();
        for (int i = tid; i < TN * HIN2; i += NT) {
            int tn = i / HIN2, r = i - tn * HIN2;
            int iy = r / HIN, ix = r - iy * HIN;
            float v = in[((size_t)(n0 + tn) * CIN + ci) * HIN2 + r];
            if (APPLY) { v = v * scv + shv; v = v > 0.f ? v : 0.f; }
            pl[tn * HIN2 + iy * HIN + (ix >> 1) + (ix & 1) * HALF] = v;
        }
        __syncthreads();
#pragma unroll
        for (int tap = 0; tap < 9; tap++) {
            float wv[TCO];
#pragma unroll
            for (int t = 0; t < TCO; t++) wv[t] = ws[t * CIN * 9 + ci * 9 + tap];
#pragma unroll
            for (int p = 0; p < P; p++) {
                int a = adr[p][tap];
                if (a >= 0) {
#pragma unroll
                    for (int tn = 0; tn < TN; tn++) {
                        float v = pl[tn * HIN2 + a];
#pragma unroll
                        for (int t = 0; t < TCO; t++) acc[t][tn][p] += v * wv[t];
                    }
                }
            }
        }
    }

#pragma unroll
    for (int p = 0; p < P; p++) {
        int q = tid + p * NT;
        if (q < HOUT2) {
#pragma unroll
            for (int tn = 0; tn < TN; tn++)
#pragma unroll
                for (int t = 0; t < TCO; t++)
                    out[((size_t)(n0 + tn) * COUT + co0 + t) * HOUT2 + q] = acc[t][tn][p];
        }
    }
}

// ---------------- head ----------------
__global__ void avgpool_k() {
    int n = blockIdx.x, c = threadIdx.x;
    float sc = g_scale[448 + c], sh = g_shift[448 + c];
    const float* p = g_c4 + (size_t)(n * 512 + c) * 49;
    float s = 0.f;
#pragma unroll
    for (int i = 0; i < 49; i++) { float v = p[i] * sc + sh; s += v > 0.f ? v : 0.f; }
    g_feats[n * 512 + c] = s * (1.f / 49.f);
}

__global__ void enc_k(const float* CK pw, const float* CK pb) {
    int n = blockIdx.x, o = threadIdx.x;
    __shared__ float fr[512];
    fr[o] = g_feats[n * 512 + o];
    __syncthreads();
    float acc = pb[o];
    for (int k = 0; k < 512; k++) acc += fr[k] * pw[k * 512 + o];
    g_enc[n * 512 + o] = acc;
}

__global__ void h0c0_k(const float* CK ihw, const float* CK ihb,
                       const float* CK icw, const float* CK icb) {
    int n = blockIdx.x, o = threadIdx.x;
    __shared__ float er[512];
    er[o] = g_enc[n * 512 + o];
    __syncthreads();
    float ah = ihb[o], ac = icb[o];
    for (int k = 0; k < 512; k++) {
        float e = er[k];
        ah += e * ihw[k * 512 + o];
        ac += e * icw[k * 512 + o];
    }
    g_h[n * 512 + o]   = tanhf(ah);
    g_cst[n * 512 + o] = tanhf(ac);
}

// ---------------- persistent LSTM ----------------
__device__ __forceinline__ float sigf(float x) { return 1.f / (1.f + expf(-x)); }

#define LSTM_NBLK 64
#define WP 516

__global__ void lstm_k(const float* CK whh) {
    extern __shared__ float sm[];
    float* wsm = sm;
    float* hbf = sm + 32 * WP;
    float* gsm = hbf + 32 * WP;
    __shared__ float bsum_s[32];

    const int tid = threadIdx.x;
    const int jb = blockIdx.x * 8;

    for (int i = tid; i < 32 * 128; i += 256) {
        int r = i >> 7, k4 = i & 127;
        int row = ((r >> 3) * 512) + jb + (r & 7);
        *((float4*)(wsm + r * WP) + k4) = *((const float4*)(whh + (size_t)row * 512) + k4);
    }
    if (tid < 32) bsum_s[tid] = g_bsum[((tid >> 3) * 512) + jb + (tid & 7)];

    const int b_own = tid >> 3, j_own = tid & 7;
    float c = g_cst[b_own * 512 + jb + j_own];

    for (int i = tid; i < 32 * 128; i += 256) {
        int b = i >> 7, k4 = i & 127;
        *((float4*)(hbf + b * WP) + k4) = __ldcg((const float4*)(g_h + b * 512) + k4);
    }
    __syncthreads();

    const int half = tid >> 7;
    const int tt = tid & 127;
    const int r0 = tt & 15;
    const int b0 = (tt >> 4) * 4;
    const int kb = half * 64;

    const float4* wA = (const float4*)(wsm + r0 * WP) + kb;
    const float4* wB = (const float4*)(wsm + (r0 + 16) * WP) + kb;

    for (int t = 0; t < 20; t++) {
        float a0[4] = {0.f, 0.f, 0.f, 0.f};
        float a1[4] = {0.f, 0.f, 0.f, 0.f};
        const float4* h0 = (const float4*)(hbf + (b0 + 0) * WP) + kb;
        const float4* h1 = (const float4*)(hbf + (b0 + 1) * WP) + kb;
        const float4* h2 = (const float4*)(hbf + (b0 + 2) * WP) + kb;
        const float4* h3 = (const float4*)(hbf + (b0 + 3) * WP) + kb;
#pragma unroll 8
        for (int k = 0; k < 64; k++) {
            float4 w0 = wA[k], w1 = wB[k];
            float4 hv;
            hv = h0[k];
            a0[0] += w0.x * hv.x + w0.y * hv.y + w0.z * hv.z + w0.w * hv.w;
            a1[0] += w1.x * hv.x + w1.y * hv.y + w1.z * hv.z + w1.w * hv.w;
            hv = h1[k];
            a0[1] += w0.x * hv.x + w0.y * hv.y + w0.z * hv.z + w0.w * hv.w;
            a1[1] += w1.x * hv.x + w1.y * hv.y + w1.z * hv.z + w1.w * hv.w;
            hv = h2[k];
            a0[2] += w0.x * hv.x + w0.y * hv.y + w0.z * hv.z + w0.w * hv.w;
            a1[2] += w1.x * hv.x + w1.y * hv.y + w1.z * hv.z + w1.w * hv.w;
            hv = h3[k];
            a0[3] += w0.x * hv.x + w0.y * hv.y + w0.z * hv.z + w0.w * hv.w;
            a1[3] += w1.x * hv.x + w1.y * hv.y + w1.z * hv.z + w1.w * hv.w;
        }
#pragma unroll
        for (int j = 0; j < 4; j++) {
            gsm[half * 1056 + r0 * 33 + b0 + j]        = a0[j];
            gsm[half * 1056 + (r0 + 16) * 33 + b0 + j] = a1[j];
        }
        __syncthreads();

        const int m = b_own * 20 + t;
        const float* gxp = g_gx + (size_t)m * 2048 + jb + j_own;
        float iv = gsm[j_own * 33 + b_own]        + gsm[1056 + j_own * 33 + b_own]        + gxp[0]    + bsum_s[j_own];
        float fv = gsm[(8 + j_own) * 33 + b_own]  + gsm[1056 + (8 + j_own) * 33 + b_own]  + gxp[512]  + bsum_s[8 + j_own];
        float gv = gsm[(16 + j_own) * 33 + b_own] + gsm[1056 + (16 + j_own) * 33 + b_own] + gxp[1024] + bsum_s[16 + j_own];
        float ov = gsm[(24 + j_own) * 33 + b_own] + gsm[1056 + (24 + j_own) * 33 + b_own] + gxp[1536] + bsum_s[24 + j_own];
        c = sigf(fv) * c + sigf(iv) * tanhf(gv);
        float h = sigf(ov) * tanhf(c);
        g_h[b_own * 512 + jb + j_own] = h;
        g_hs[(size_t)m * 512 + jb + j_own] = h;

        __syncthreads();
        if (tid == 0) {
            __threadfence();
            if (atomicAdd(&g_count, 1) == LSTM_NBLK - 1) {
                g_count = 0;
                __threadfence();
                atomicExch(&g_gen, t + 1);
            } else {
                while (((volatile int*)&g_gen)[0] < t + 1) {}
                __threadfence();
            }
        }
        __syncthreads();

        for (int i = tid; i < 32 * 128; i += 256) {
            int b = i >> 7, k4 = i & 127;
            *((float4*)(hbf + b * WP) + k4) = __ldcg((const float4*)(g_h + b * 512) + k4);
        }
        __syncthreads();
    }
}

// ---------------- launch ----------------
extern "C" void kernel_launch(void* const* d_in, const int* in_sizes, int n_in,
                              void* d_out, int out_size) {
    const float* images = (const float*)d_in[0];
    const int*   caps   = (const int*)d_in[1];
    const float* w1  = (const float*)d_in[2];
    const float* g1  = (const float*)d_in[3];
    const float* be1 = (const float*)d_in[4];
    const float* w2  = (const float*)d_in[5];
    const float* g2  = (const float*)d_in[6];
    const float* be2 = (const float*)d_in[7];
    const float* w3  = (const float*)d_in[8];
    const float* g3  = (const float*)d_in[9];
    const float* be3 = (const float*)d_in[10];
    const float* w4  = (const float*)d_in[11];
    const float* g4  = (const float*)d_in[12];
    const float* be4 = (const float*)d_in[13];
    const float* pw  = (const float*)d_in[14];
    const float* pb  = (const float*)d_in[15];
    const float* emb = (const float*)d_in[16];
    const float* ihw = (const float*)d_in[17];
    const float* ihb = (const float*)d_in[18];
    const float* icw = (const float*)d_in[19];
    const float* icb = (const float*)d_in[20];
    const float* wih = (const float*)d_in[21];
    const float* whh = (const float*)d_in[22];
    const float* bih = (const float*)d_in[23];
    const float* bhh = (const float*)d_in[24];
    const float* ow  = (const float*)d_in[25];
    const float* ob  = (const float*)d_in[26];

    float *pC1, *pPool, *pC2, *pC3, *pC4, *pXs, *pGx, *pHs, *pWT;
    cudaGetSymbolAddress((void**)&pC1, g_c1);
    cudaGetSymbolAddress((void**)&pPool, g_pool);
    cudaGetSymbolAddress((void**)&pC2, g_c2);
    cudaGetSymbolAddress((void**)&pC3, g_c3);
    cudaGetSymbolAddress((void**)&pC4, g_c4);
    cudaGetSymbolAddress((void**)&pXs, g_xs);
    cudaGetSymbolAddress((void**)&pGx, g_gx);
    cudaGetSymbolAddress((void**)&pHs, g_hs);
    cudaGetSymbolAddress((void**)&pWT, g_wihT);

    const int smem2 = (8 * 64 * 9 + 56 * 56) * 4;
    const int smem3 = (8 * 128 * 9 + 4 * 28 * 28) * 4;
    const int smem4 = (8 * 256 * 9 + 8 * 14 * 14) * 4;
    const int smemL = (32 * WP + 32 * WP + 2 * 32 * 33) * 4;
    cudaFuncSetAttribute(conv3x3s2_k<128, 28, 14, 8, 4, 224, 1, true>,
                         cudaFuncAttributeMaxDynamicSharedMemorySize, smem3);
    cudaFuncSetAttribute(conv3x3s2_k<256, 14, 7, 8, 8, 64, 1, true>,
                         cudaFuncAttributeMaxDynamicSharedMemorySize, smem4);
    cudaFuncSetAttribute(lstm_k, cudaFuncAttributeMaxDynamicSharedMemorySize, smemL);

    init_k<<<1, 32>>>();                                              // 0
    biassum_k<<<8, 256>>>(bih, bhh);                                  // 1
    xgather_k<<<640, 512>>>(emb, caps);                               // 2
    wihT_k<<<dim3(16, 64), 256>>>(wih);                               // 3
    conv1_k<<<dim3(28, 8, 32), 112>>>(images, w1);                    // 4
    gemm_wmma_k<<<dim3(16, 5), 256>>>(pXs, pWT, nullptr, pGx, 640, 2048, 512); // 5 (profiled)

    bn_part_k<<<dim3(64, 16), 256>>>(pC1, 64, 112 * 112, 2);
    bn_fin_k<<<1, 64>>>(g1, be1, 64, 16, 1.f / (32.f * 112 * 112), 0);
    pool_k<<<dim3(13, 64, 32), 256>>>();

    conv3x3s2_k<64, 56, 28, 8, 1, 256, 4, false>
        <<<dim3(16, 32), 256, smem2>>>(pPool, w2, pC2, 128, 0);
    bn_part_k<<<dim3(128, 8), 256>>>(pC2, 128, 28 * 28, 4);
    bn_fin_k<<<2, 64>>>(g2, be2, 128, 8, 1.f / (32.f * 28 * 28), 64);

    conv3x3s2_k<128, 28, 14, 8, 4, 224, 1, true>
        <<<dim3(32, 8), 224, smem3>>>(pC2, w3, pC3, 256, 64);
    bn_part_k<<<dim3(256, 4), 256>>>(pC3, 256, 14 * 14, 8);
    bn_fin_k<<<4, 64>>>(g3, be3, 256, 4, 1.f / (32.f * 14 * 14), 192);

    conv3x3s2_k<256, 14, 7, 8, 8, 64, 1, true>
        <<<dim3(64, 4), 64, smem4>>>(pC3, w4, pC4, 512, 192);
    bn_part_k<<<dim3(512, 2), 256>>>(pC4, 512, 7 * 7, 16);
    bn_fin_k<<<8, 64>>>(g4, be4, 512, 2, 1.f / (32.f * 7 * 7), 448);

    avgpool_k<<<32, 512>>>();
    enc_k<<<32, 512>>>(pw, pb);
    h0c0_k<<<32, 512>>>(ihw, ihb, icw, icb);

    lstm_k<<<LSTM_NBLK, 256, smemL>>>(whh);

    gemm_wmma_k<<<dim3(250, 5), 256>>>(pHs, ow, ob, (float*)d_out, 640, 32000, 512);
}